// round 5
// baseline (speedup 1.0000x reference)
#include <cuda_runtime.h>
#include <cstdint>

#define NTH   512
#define KSEL  100
#define CAP   2048
#define NMAX  16384
#define FULLM 0xffffffffu

struct SM {
    unsigned keys[NMAX];              // 64 KB
    unsigned long long cand[CAP];     // 16 KB
    unsigned wcnt[16][32];            // 2 KB
    float s_data[KSEL * 16];
    float s_box[KSEL * 4];
    float s_val[KSEL];
    float s_bel[KSEL];
    float s_area[KSEL];
    int   s_keep[KSEL];
    int   s_vld[KSEL];
    int   s_nk[KSEL];
    unsigned sup[KSEL][4];
    unsigned km[4];
    int      sC;
    unsigned sAbove;
    unsigned sT10;
    unsigned s_cnt;
};

__device__ __forceinline__ unsigned fkey(float f) {
    unsigned u = __float_as_uint(f);
    return (u & 0x80000000u) ? ~u : (u | 0x80000000u);
}

// ballot-transpose: count one element-per-lane into 32 lane-resident counters.
// bin5 in [0,32); 'valid' masks participation. Lane L accumulates #elements with bin==L.
__device__ __forceinline__ void tcnt5(unsigned bin5, bool valid, unsigned& cnt, int lane) {
    unsigned vb = __ballot_sync(FULLM, valid);
    unsigned b0 = __ballot_sync(FULLM, valid && (bin5 & 1u));
    unsigned b1 = __ballot_sync(FULLM, valid && (bin5 & 2u));
    unsigned b2 = __ballot_sync(FULLM, valid && (bin5 & 4u));
    unsigned b3 = __ballot_sync(FULLM, valid && (bin5 & 8u));
    unsigned b4 = __ballot_sync(FULLM, valid && (bin5 & 16u));
    unsigned m = vb;
    m &= (lane & 1)  ? b0 : ~b0;
    m &= (lane & 2)  ? b1 : ~b1;
    m &= (lane & 4)  ? b2 : ~b2;
    m &= (lane & 8)  ? b3 : ~b3;
    m &= (lane & 16) ? b4 : ~b4;
    cnt += __popc(m);
}

__global__ __launch_bounds__(NTH) void pp_kernel(
    const float* __restrict__ blk_logit,
    const float* __restrict__ lin_logit,
    const float* __restrict__ chr_logit,
    const float* __restrict__ blk_raw,
    const float* __restrict__ lin_raw,
    const float* __restrict__ chr_raw,
    const float* __restrict__ tsz,
    float* __restrict__ out,
    int B, int NB, int NL, int NC)
{
    // Tail-balanced remap: heavy CTAs (lvl1/lvl2) first, light lvl0 in the tail wave.
    const int bid = blockIdx.x;
    int b, lvl;
    if (bid < 2 * B) { lvl = 1 + (bid & 1); b = bid >> 1; }
    else             { lvl = 0; b = bid - 2 * B; }
    const int tid = threadIdx.x;
    const int wid = tid >> 5;
    const int lane = tid & 31;

    int N, PN = 0, ef = 1;
    const float *logit, *raw, *praw = nullptr;
    bool bez = false;
    if (lvl == 0)      { N = NB; logit = blk_logit; raw = blk_raw; }
    else if (lvl == 1) { N = NL; logit = lin_logit; raw = lin_raw; praw = blk_raw; PN = NB; ef = 4; }
    else               { N = NC; logit = chr_logit; raw = chr_raw; praw = lin_raw; PN = NL; ef = 1; bez = true; }

    extern __shared__ unsigned char smraw[];
    SM& sm = *(SM*)smraw;

    if (tid == 0) sm.s_cnt = 0;

    // ---- Pass 1: keys -> smem + coarse 32-bin ballot-transpose count (key>>27) ----
    const float4* lp4 = (const float4*)(logit + (size_t)b * N);
    const int n4 = N >> 2;
    const int iters = (n4 + NTH - 1) / NTH;
    unsigned cnt1 = 0;
    for (int it = 0; it < iters; ++it) {
        int i = it * NTH + tid;
        bool val = i < n4;
        float4 v;
        unsigned k0 = 0, k1 = 0, k2 = 0, k3 = 0;
        if (val) {
            v = lp4[i];
            k0 = fkey(v.x); k1 = fkey(v.y); k2 = fkey(v.z); k3 = fkey(v.w);
            ((uint4*)sm.keys)[i] = make_uint4(k0, k1, k2, k3);
        }
        tcnt5(k0 >> 27, val, cnt1, lane);
        tcnt5(k1 >> 27, val, cnt1, lane);
        tcnt5(k2 >> 27, val, cnt1, lane);
        tcnt5(k3 >> 27, val, cnt1, lane);
    }
    sm.wcnt[wid][lane] = cnt1;
    __syncthreads();

    // ---- Reduce coarse counts; find coarse bin C* containing the 100th value ----
    if (tid < 32) {
        unsigned c = 0;
        #pragma unroll
        for (int w = 0; w < 16; ++w) c += sm.wcnt[w][tid];
        unsigned s = c;
        #pragma unroll
        for (int off = 1; off < 32; off <<= 1) {
            unsigned t = __shfl_down_sync(FULLM, s, off);
            if (tid + off < 32) s += t;
        }
        unsigned ball = __ballot_sync(FULLM, s >= (unsigned)KSEL);
        int C = 31 - __clz(ball);
        if (tid == C) { sm.sC = C; sm.sAbove = s - c; }
    }
    __syncthreads();
    const int C = sm.sC;

    // ---- Pass 2: refine 5 more key bits within bin C* ----
    unsigned cnt2 = 0;
    for (int it = 0; it < iters; ++it) {
        int i = it * NTH + tid;
        bool val = i < n4;
        uint4 kk = val ? ((const uint4*)sm.keys)[i] : make_uint4(0, 0, 0, 0);
        bool v0 = val && (int)(kk.x >> 27) == C;
        bool v1 = val && (int)(kk.y >> 27) == C;
        bool v2 = val && (int)(kk.z >> 27) == C;
        bool v3 = val && (int)(kk.w >> 27) == C;
        tcnt5((kk.x >> 22) & 31u, v0, cnt2, lane);
        tcnt5((kk.y >> 22) & 31u, v1, cnt2, lane);
        tcnt5((kk.z >> 22) & 31u, v2, cnt2, lane);
        tcnt5((kk.w >> 22) & 31u, v3, cnt2, lane);
    }
    sm.wcnt[wid][lane] = cnt2;
    __syncthreads();

    if (tid < 32) {
        unsigned target = (unsigned)KSEL - sm.sAbove;   // sAbove < KSEL by construction
        unsigned c = 0;
        #pragma unroll
        for (int w = 0; w < 16; ++w) c += sm.wcnt[w][tid];
        unsigned s = c;
        #pragma unroll
        for (int off = 1; off < 32; off <<= 1) {
            unsigned t = __shfl_down_sync(FULLM, s, off);
            if (tid + off < 32) s += t;
        }
        unsigned ball = __ballot_sync(FULLM, s >= target);
        int F = 31 - __clz(ball);
        if (tid == F) sm.sT10 = ((unsigned)C << 5) | (unsigned)F;
    }
    __syncthreads();
    const unsigned T10 = sm.sT10;

    // ---- Collect candidates with (key >> 22) >= T10 (few hundred atomics only) ----
    for (int it = 0; it < iters; ++it) {
        int i = it * NTH + tid;
        if (i < n4) {
            uint4 kk = ((const uint4*)sm.keys)[i];
            unsigned ks[4] = { kk.x, kk.y, kk.z, kk.w };
            #pragma unroll
            for (int q = 0; q < 4; ++q) {
                if ((ks[q] >> 22) >= T10) {
                    unsigned pos = atomicAdd(&sm.s_cnt, 1u);
                    if (pos < CAP)
                        sm.cand[pos] = ((unsigned long long)ks[q] << 32) | (unsigned)(~(4 * i + q));
                }
            }
        }
    }
    __syncthreads();
    int cnt = (int)sm.s_cnt; if (cnt > CAP) cnt = CAP;
    int P = 128; while (P < cnt) P <<= 1;
    for (int i = tid; i < P; i += NTH) if (i >= cnt) sm.cand[i] = 0ULL;
    __syncthreads();

    // ---- Bitonic sort descending (composite (key, ~idx): stable lower-index first) ----
    for (int k = 2; k <= P; k <<= 1) {
        for (int j = k >> 1; j > 0; j >>= 1) {
            for (int i = tid; i < P; i += NTH) {
                int ixj = i ^ j;
                if (ixj > i) {
                    unsigned long long a = sm.cand[i], c2 = sm.cand[ixj];
                    bool desc = ((i & k) == 0);
                    if (desc ? (a < c2) : (a > c2)) { sm.cand[i] = c2; sm.cand[ixj] = a; }
                }
            }
            __syncthreads();
        }
    }

    const float ih = tsz[2 * b + 0];
    const float iw = tsz[2 * b + 1];

    // ---- Per-row decode ----
    if (tid < KSEL) {
        unsigned long long e = sm.cand[tid];
        unsigned key = (unsigned)(e >> 32);
        int idx = (int)(~((unsigned)e));
        unsigned u = (key & 0x80000000u) ? (key ^ 0x80000000u) : ~key;
        float lg = __uint_as_float(u);
        float prob = 1.0f / (1.0f + expf(-lg));
        sm.s_val[tid] = prob;
        sm.s_keep[tid] = prob > 0.1f;

        float bx0, bx1, bx2, bx3;
        if (!bez) {
            const float* rp = raw + ((size_t)b * N + idx) * 4;
            float cx = rp[0], cy = rp[1], bw = rp[2], bh = rp[3];
            bx0 = (cx - 0.5f * bw) * iw;
            bx1 = (cy - 0.5f * bh) * ih;
            bx2 = (cx + 0.5f * bw) * iw;
            bx3 = (cy + 0.5f * bh) * ih;
            if (lvl == 0) {
                bx0 = fminf(fmaxf(bx0, 0.f), iw);
                bx1 = fminf(fmaxf(bx1, 0.f), ih);
                bx2 = fminf(fmaxf(bx2, 0.f), iw);
                bx3 = fminf(fmaxf(bx3, 0.f), ih);
            }
            sm.s_data[tid * 16 + 0] = bx0; sm.s_data[tid * 16 + 1] = bx1;
            sm.s_data[tid * 16 + 2] = bx2; sm.s_data[tid * 16 + 3] = bx3;
        } else {
            const float* rp = raw + ((size_t)b * N + idx) * 16;
            float cpt[16];
            #pragma unroll
            for (int q = 0; q < 8; ++q) {
                cpt[2 * q + 0] = rp[2 * q + 0] * ih;
                cpt[2 * q + 1] = rp[2 * q + 1] * iw;
            }
            #pragma unroll
            for (int q = 0; q < 16; ++q) sm.s_data[tid * 16 + q] = cpt[q];
            float mn0 = 1e30f, mn1 = 1e30f, mx0 = -1e30f, mx1 = -1e30f;
            #pragma unroll
            for (int s2 = 0; s2 < 10; ++s2) {
                float t  = (float)s2 / 9.0f;
                float ti = 1.0f - t;
                float c0 = ti * ti * ti, c1 = 3.f * t * ti * ti;
                float c2 = 3.f * t * t * ti, c3 = t * t * t;
                float p0 = c0 * cpt[0] + c1 * cpt[2] + c2 * cpt[4]  + c3 * cpt[6];
                float p1 = c0 * cpt[1] + c1 * cpt[3] + c2 * cpt[5]  + c3 * cpt[7];
                float q0 = c0 * cpt[8] + c1 * cpt[10] + c2 * cpt[12] + c3 * cpt[14];
                float q1 = c0 * cpt[9] + c1 * cpt[11] + c2 * cpt[13] + c3 * cpt[15];
                mn0 = fminf(mn0, fminf(p0, q0));
                mn1 = fminf(mn1, fminf(p1, q1));
                mx0 = fmaxf(mx0, fmaxf(p0, q0));
                mx1 = fmaxf(mx1, fmaxf(p1, q1));
            }
            bx0 = mn0; bx1 = mn1; bx2 = mx0; bx3 = mx1;
        }
        sm.s_box[tid * 4 + 0] = bx0; sm.s_box[tid * 4 + 1] = bx1;
        sm.s_box[tid * 4 + 2] = bx2; sm.s_box[tid * 4 + 3] = bx3;
        float area = (bx2 - bx0) * (bx3 - bx1);
        sm.s_area[tid] = area;

        if (lvl > 0) {
            const float* pr = praw + ((size_t)b * PN + idx / ef) * 4;
            float pcx = pr[0], pcy = pr[1], pw = pr[2], ph = pr[3];
            float px0 = (pcx - 0.5f * pw) * iw, py0 = (pcy - 0.5f * ph) * ih;
            float px1 = (pcx + 0.5f * pw) * iw, py1 = (pcy + 0.5f * ph) * ih;
            float ix1 = fmaxf(bx0, px0), iy1 = fmaxf(bx1, py0);
            float ix2 = fminf(bx2, px1), iy2 = fminf(bx3, py1);
            float inter = fmaxf(ix2 - ix1, 0.f) * fmaxf(iy2 - iy1, 0.f);
            float belong = inter / (area + 1e-6f);
            sm.s_bel[tid] = belong;
            sm.s_vld[tid] = belong > 0.6f;
        }
    }
    __syncthreads();

    // ---- Serial reductions: keep fallback + belong-valid fallback (proven R1 path) ----
    if (tid == 0) {
        bool any = false;
        for (int r = 0; r < KSEL; ++r) any = any || (sm.s_keep[r] != 0);
        if (!any) sm.s_keep[0] = 1;
        if (lvl > 0) {
            bool anyVK = false;
            float best = -1e38f; int bi = 0;
            for (int r = 0; r < KSEL; ++r) {
                bool kp = sm.s_keep[r] != 0;
                if (kp && sm.s_vld[r]) anyVK = true;
                float v2 = kp ? sm.s_bel[r] : -1e38f;
                if (v2 > best) { best = v2; bi = r; }
            }
            for (int r = 0; r < KSEL; ++r) {
                int m = anyVK ? (sm.s_keep[r] && sm.s_vld[r])
                              : (sm.s_keep[r] && (r == bi));
                sm.s_nk[r] = m;
            }
        } else {
            for (int r = 0; r < KSEL; ++r) sm.s_nk[r] = sm.s_keep[r];
        }
    }
    __syncthreads();

    // ---- NMS: parallel suppression-bitmask matrix (barrier-free; proven in R2) ----
    if (tid < KSEL) {
        float ax0 = sm.s_box[tid * 4 + 0], ay0 = sm.s_box[tid * 4 + 1];
        float ax1 = sm.s_box[tid * 4 + 2], ay1 = sm.s_box[tid * 4 + 3];
        float aa = sm.s_area[tid];
        unsigned m0 = 0, m1 = 0, m2 = 0, m3 = 0;
        for (int j = tid + 1; j < KSEL; ++j) {
            float bx0 = sm.s_box[j * 4 + 0], by0 = sm.s_box[j * 4 + 1];
            float bx1 = sm.s_box[j * 4 + 2], by1 = sm.s_box[j * 4 + 3];
            float ix0 = fmaxf(ax0, bx0), iy0 = fmaxf(ay0, by0);
            float ix1 = fminf(ax1, bx1), iy1 = fminf(ay1, by1);
            float inter = fmaxf(ix1 - ix0, 0.f) * fmaxf(iy1 - iy0, 0.f);
            float iou = inter / (aa + sm.s_area[j] - inter);
            if (iou > 0.1f) {
                unsigned bit = 1u << (j & 31);
                int w = j >> 5;
                if (w == 0) m0 |= bit; else if (w == 1) m1 |= bit;
                else if (w == 2) m2 |= bit; else m3 |= bit;
            }
        }
        sm.sup[tid][0] = m0; sm.sup[tid][1] = m1;
        sm.sup[tid][2] = m2; sm.sup[tid][3] = m3;
    }
    if (tid < 128) {
        unsigned bal = __ballot_sync(FULLM, (tid < KSEL) && sm.s_nk[tid]);
        if (lane == 0) sm.km[wid] = bal;
    }
    __syncthreads();

    if (tid == 0) {
        unsigned k0 = sm.km[0], k1 = sm.km[1], k2 = sm.km[2], k3 = sm.km[3];
        for (int i = 0; i < KSEL; ++i) {
            unsigned word = (i < 32) ? k0 : (i < 64) ? k1 : (i < 96) ? k2 : k3;
            if ((word >> (i & 31)) & 1u) {
                k0 &= ~sm.sup[i][0];
                k1 &= ~sm.sup[i][1];
                k2 &= ~sm.sup[i][2];
                k3 &= ~sm.sup[i][3];
            }
        }
        sm.km[0] = k0; sm.km[1] = k1; sm.km[2] = k2; sm.km[3] = k3;
    }
    __syncthreads();

    // ---- Write outputs ----
    size_t nbd = (size_t)B * 400;
    size_t nsc = (size_t)B * 100;
    size_t oD, oS, oK;
    if (lvl == 0)      { oD = 0; oS = nbd; oK = nbd + nsc; }
    else if (lvl == 1) { size_t base = nbd + 2 * nsc; oD = base; oS = base + nbd; oK = oS + nsc; }
    else               { size_t base = 2 * (nbd + 2 * nsc); oD = base; oS = base + (size_t)B * 1600; oK = oS + nsc; }

    if (tid < KSEL) {
        bool nk = (sm.km[tid >> 5] >> (tid & 31)) & 1u;
        out[oS + (size_t)b * 100 + tid] = nk ? sm.s_val[tid] : 0.f;
        out[oK + (size_t)b * 100 + tid] = nk ? 1.f : 0.f;
        int D = bez ? 16 : 4;
        float* dp = out + oD + ((size_t)b * 100 + tid) * D;
        for (int d2 = 0; d2 < D; ++d2) dp[d2] = nk ? sm.s_data[tid * 16 + d2] : 0.f;
    }
}

extern "C" void kernel_launch(void* const* d_in, const int* in_sizes, int n_in,
                              void* d_out, int out_size) {
    const float* blk_logit = (const float*)d_in[0];
    const float* lin_logit = (const float*)d_in[1];
    const float* chr_logit = (const float*)d_in[2];
    const float* blk_raw   = (const float*)d_in[3];
    const float* lin_raw   = (const float*)d_in[4];
    const float* chr_raw   = (const float*)d_in[5];
    const float* tsz       = (const float*)d_in[6];
    float* out = (float*)d_out;

    int B  = in_sizes[6] / 2;
    int NB = in_sizes[0] / B;
    int NL = in_sizes[1] / B;
    int NC = in_sizes[2] / B;

    cudaFuncSetAttribute(pp_kernel, cudaFuncAttributeMaxDynamicSharedMemorySize, (int)sizeof(SM));
    pp_kernel<<<3 * B, NTH, sizeof(SM)>>>(blk_logit, lin_logit, chr_logit,
                                          blk_raw, lin_raw, chr_raw, tsz, out,
                                          B, NB, NL, NC);
}